// round 5
// baseline (speedup 1.0000x reference)
#include <cuda_runtime.h>
#include <cuda_bf16.h>
#include <cstdint>

#define EE    256
#define HH    4
#define DH    64
#define BB    8
#define CC    32
#define RR    255
#define SS    256
#define HID   1024
#define NBC   (BB*CC)      // 256 tokens
#define TOK   8
#define NSL   8
#define NCH   8            // attention chunks per token (32 positions each)
#define CHP   32           // positions per chunk
#define LN_EPS 1e-5f

// ---------------- device scratch ----------------
__device__ float g_u[HH*EE];
__device__ float g_cb[HH];
__device__ float g_bias2[EE];
__device__ float g_M2T[HID*EE];       // [j][f]
__device__ float g_W1T[EE*HID];       // [e][j]
__device__ float g_W2T[HID*EE];       // [j][f]
__device__ float g_xbar[NBC*HID];     // [t][j]
__device__ float g_ln[NBC*EE];
__device__ float g_hid[NBC*HID];
__device__ float g_part[NSL*NBC*EE];
__device__ float g_part2[NSL*NBC*EE];
__device__ float g_pxc[NBC*NCH*HH*EE];  // chunk partial weighted sums (8MB)
__device__ float g_cm[NBC*NCH*HH];      // chunk max
__device__ float g_cs[NBC*NCH*HH];      // chunk expsum

// ---------------- kernel: tiny prep (u, cb, bias2) ----------------
__global__ void prep_kernel(const float* __restrict__ cls,
                            const float* __restrict__ w_qkv,
                            const float* __restrict__ b_qkv,
                            const float* __restrict__ w_out,
                            const float* __restrict__ b_out) {
    __shared__ float s_cls[EE];
    __shared__ float s_q0[EE];
    int tid = threadIdx.x;
    s_cls[tid] = cls[tid];
    __syncthreads();
    float acc = b_qkv[tid];
    const float* wr = w_qkv + (size_t)tid * EE;
    #pragma unroll 8
    for (int e = 0; e < EE; e++) acc += wr[e] * s_cls[e];
    s_q0[tid] = acc;
    __syncthreads();

    const float scale = 0.125f;
    for (int h = 0; h < HH; h++) {
        float s = 0.f;
        #pragma unroll 8
        for (int d = 0; d < DH; d++)
            s += s_q0[h*DH + d] * w_qkv[(size_t)(EE + h*DH + d) * EE + tid];
        g_u[h*EE + tid] = s * scale;
    }
    if (tid < HH) {
        float s = 0.f;
        for (int d = 0; d < DH; d++)
            s += s_q0[tid*DH + d] * b_qkv[EE + tid*DH + d];
        g_cb[tid] = s * scale;
    }
    float s2 = b_out[tid];
    const float* wo = w_out + (size_t)tid * EE;
    #pragma unroll 8
    for (int g = 0; g < EE; g++) s2 += wo[g] * b_qkv[2*EE + g];
    g_bias2[tid] = s2;
}

// ---------------- fused kernel: attn chunks [0,2048) | M2T [2048,2112) | transposes [2112,2624) ----------------
__global__ __launch_bounds__(256) void fused_kernel(const float* __restrict__ x,
                             const int* __restrict__ real_rows,
                             const float* __restrict__ cls,
                             const float* __restrict__ w_qkv,
                             const float* __restrict__ w_out,
                             const float* __restrict__ w1,
                             const float* __restrict__ w2) {
    int bi = blockIdx.x;
    int tid = threadIdx.x;

    if (bi < NBC*NCH) {
        // ================= attention chunk =================
        int bc = bi >> 3, c = bi & 7;
        int b = bc >> 5;
        int nk = real_rows[b] + 1;
        int p0 = c * CHP;
        if (p0 >= nk) return;
        int nvalid = min(CHP, nk - p0);

        __shared__ __align__(16) float sx[CHP][260];   // padded rows
        __shared__ __align__(16) float s_u[HH*EE];
        __shared__ float s_sc[HH][CHP];
        __shared__ float s_w[HH][CHP];
        __shared__ float s_m[HH], s_sum[HH], s_cb[HH];

        #pragma unroll
        for (int i = 0; i < 4; i++) s_u[i*256 + tid] = g_u[i*256 + tid];
        if (tid < HH) s_cb[tid] = g_cb[tid];

        // stage rows: row r corresponds to global pos p0+r
        const float* xbase = x + (size_t)bc * RR * EE;
        for (int idx = tid; idx < nvalid*64; idx += 256) {
            int r = idx >> 6, q = idx & 63;
            int pos = p0 + r;
            const float4* src = (pos == 0) ? ((const float4*)cls + q)
                              : ((const float4*)(xbase + (size_t)(pos-1)*EE) + q);
            *(float4*)&sx[r][q*4] = *src;
        }
        __syncthreads();

        // scores: 2 threads per (p,h) pair
        {
            int pair = tid >> 1, sub = tid & 1;
            int p = pair >> 2, h = pair & 3;
            float acc = 0.f;
            if (p < nvalid) {
                const float4* xr = (const float4*)&sx[p][sub*128];
                const float4* ur = (const float4*)&s_u[h*EE + sub*128];
                #pragma unroll 8
                for (int i = 0; i < 32; i++) {
                    float4 xv = xr[i], uv = ur[i];
                    acc += xv.x*uv.x + xv.y*uv.y + xv.z*uv.z + xv.w*uv.w;
                }
            }
            acc += __shfl_xor_sync(0xffffffffu, acc, 1);
            if (sub == 0) s_sc[h][p] = (p < nvalid) ? acc + s_cb[h] : -3.0e38f;
        }
        __syncthreads();

        // local softmax per head (warps 0..3)
        int warp = tid >> 5, lane = tid & 31;
        if (warp < HH) {
            int h = warp;
            float v = s_sc[h][lane];
            float m = v;
            #pragma unroll
            for (int o = 16; o; o >>= 1) m = fmaxf(m, __shfl_xor_sync(0xffffffffu, m, o));
            float w = (lane < nvalid) ? __expf(v - m) : 0.f;
            float sum = w;
            #pragma unroll
            for (int o = 16; o; o >>= 1) sum += __shfl_xor_sync(0xffffffffu, sum, o);
            s_w[h][lane] = w;
            if (lane == 0) { s_m[h] = m; s_sum[h] = sum; }
        }
        __syncthreads();

        // partial weighted x-sum: thread per e
        int e = tid;
        float a0 = 0.f, a1 = 0.f, a2 = 0.f, a3 = 0.f;
        #pragma unroll 4
        for (int r = 0; r < nvalid; r++) {
            float xv = sx[r][e];
            a0 += s_w[0][r]*xv; a1 += s_w[1][r]*xv;
            a2 += s_w[2][r]*xv; a3 += s_w[3][r]*xv;
        }
        float* px = g_pxc + (size_t)bi * HH * EE;
        px[0*EE + e] = a0; px[1*EE + e] = a1;
        px[2*EE + e] = a2; px[3*EE + e] = a3;
        if (tid < HH) {
            g_cm[bi*HH + tid] = s_m[tid];
            g_cs[bi*HH + tid] = s_sum[tid];
        }
        return;
    }

    int a = bi - NBC*NCH;
    if (a < 64) {
        // ---- M2T tiled GEMM ----
        __shared__ float sa[64][64];
        __shared__ float sb[64][65];
        int h = a >> 4, e0 = ((a >> 2) & 3) * 64, f0 = (a & 3) * 64;
        for (int i = tid; i < 4096; i += 256) {
            int d = i >> 6, el = i & 63;
            sa[d][el] = w_qkv[(size_t)(2*EE + h*64 + d) * EE + e0 + el];
        }
        for (int i = tid; i < 4096; i += 256) {
            int fl = i >> 6, d = i & 63;
            sb[fl][d] = w_out[(size_t)(f0 + fl) * EE + h*64 + d];
        }
        __syncthreads();
        int tx = tid & 15, ty = tid >> 4;
        float acc[4][4] = {};
        #pragma unroll 4
        for (int d = 0; d < 64; d++) {
            float av[4], bv[4];
            #pragma unroll
            for (int i = 0; i < 4; i++) av[i] = sa[d][ty*4 + i];
            #pragma unroll
            for (int i = 0; i < 4; i++) bv[i] = sb[tx*4 + i][d];
            #pragma unroll
            for (int i = 0; i < 4; i++)
                #pragma unroll
                for (int j = 0; j < 4; j++) acc[i][j] += av[i] * bv[j];
        }
        #pragma unroll
        for (int i = 0; i < 4; i++)
            *(float4*)&g_M2T[(size_t)(h*256 + e0 + ty*4 + i) * EE + f0 + tx*4] = *(float4*)acc[i];
        return;
    }
    a -= 64;
    // ---- transposes ----
    __shared__ float s[32][33];
    const float* src; float* dst; int rows, cols, bx, by;
    if (a < 256) {             // W1 [1024][256] -> W1T [256][1024]
        src = w1; dst = g_W1T; rows = HID; cols = EE;
        bx = (a & 7) * 32; by = (a >> 3) * 32;
    } else {                   // W2 [256][1024] -> W2T [1024][256]
        a -= 256;
        src = w2; dst = g_W2T; rows = EE; cols = HID;
        bx = (a & 31) * 32; by = (a >> 5) * 32;
    }
    int tx = tid & 31, ty = tid >> 5;
    #pragma unroll
    for (int r = 0; r < 4; r++)
        s[ty + r*8][tx] = src[(size_t)(by + ty + r*8) * cols + bx + tx];
    __syncthreads();
    #pragma unroll
    for (int r = 0; r < 4; r++)
        dst[(size_t)(bx + ty + r*8) * rows + by + tx] = s[tx][ty + r*8];
}

// ---------------- kernel: combine chunk partials -> xbar (block per token) ----------------
__global__ __launch_bounds__(256) void combine_kernel(const int* __restrict__ real_rows) {
    __shared__ float s_wc[NCH][HH];
    __shared__ float s_inv[HH];
    int bc = blockIdx.x;
    int b = bc >> 5;
    int tid = threadIdx.x;
    int nk = real_rows[b] + 1;
    int nc = (nk + CHP - 1) / CHP;

    if (tid < 32) {
        int c = tid >> 2, h = tid & 3;
        float m = (c < nc) ? g_cm[(bc*NCH + c)*HH + h] : -3.0e38f;
        float M = m;
        #pragma unroll
        for (int o = 4; o < 32; o <<= 1) M = fmaxf(M, __shfl_xor_sync(0xffffffffu, M, o));
        float sm = (c < nc) ? g_cs[(bc*NCH + c)*HH + h] : 0.f;
        float wc = (c < nc) ? __expf(m - M) : 0.f;
        float dn = wc * sm;
        #pragma unroll
        for (int o = 4; o < 32; o <<= 1) dn += __shfl_xor_sync(0xffffffffu, dn, o);
        s_wc[c][h] = wc;
        if (c == 0) s_inv[h] = 1.f / dn;
    }
    __syncthreads();

    int e = tid;
    float a0 = 0.f, a1 = 0.f, a2 = 0.f, a3 = 0.f;
    for (int c = 0; c < nc; c++) {
        const float* px = g_pxc + (size_t)(bc*NCH + c) * HH * EE;
        a0 += s_wc[c][0] * px[0*EE + e];
        a1 += s_wc[c][1] * px[1*EE + e];
        a2 += s_wc[c][2] * px[2*EE + e];
        a3 += s_wc[c][3] * px[3*EE + e];
    }
    float* xb = g_xbar + (size_t)bc * HID;
    xb[0*EE + e] = a0 * s_inv[0];
    xb[1*EE + e] = a1 * s_inv[1];
    xb[2*EE + e] = a2 * s_inv[2];
    xb[3*EE + e] = a3 * s_inv[3];
}

// ---------------- kernel: mha partial GEMM ----------------
__global__ __launch_bounds__(256, 3) void mha_part_kernel() {
    __shared__ __align__(16) float s_xb[TOK][128];
    __shared__ __align__(16) float s_acc[4][TOK][EE];
    int t0 = blockIdx.x * TOK, slice = blockIdx.y;
    int tid = threadIdx.x;
    int fc = tid & 63, jg = tid >> 6;

    for (int i = tid; i < TOK*128; i += 256)
        s_xb[i >> 7][i & 127] = g_xbar[(size_t)(t0 + (i >> 7)) * HID + slice*128 + (i & 127)];
    __syncthreads();

    float4 a[TOK];
    #pragma unroll
    for (int tt = 0; tt < TOK; tt++) a[tt] = make_float4(0.f,0.f,0.f,0.f);

    const float4* Mp = ((const float4*)g_M2T) + (size_t)(slice*128 + jg*32) * 64 + fc;
    #pragma unroll 4
    for (int jl = 0; jl < 32; jl++) {
        float4 m = Mp[(size_t)jl * 64];
        int jj = jg*32 + jl;
        #pragma unroll
        for (int tt = 0; tt < TOK; tt++) {
            float xv = s_xb[tt][jj];
            a[tt].x += m.x*xv; a[tt].y += m.y*xv;
            a[tt].z += m.z*xv; a[tt].w += m.w*xv;
        }
    }
    #pragma unroll
    for (int tt = 0; tt < TOK; tt++)
        *(float4*)&s_acc[jg][tt][fc*4] = a[tt];
    __syncthreads();

    int f = tid;
    #pragma unroll
    for (int tt = 0; tt < TOK; tt++) {
        float s = s_acc[0][tt][f] + s_acc[1][tt][f] + s_acc[2][tt][f] + s_acc[3][tt][f];
        g_part[((size_t)slice * NBC + t0 + tt) * EE + f] = s;
    }
}

// ---------------- block reduce (256 threads) ----------------
__device__ __forceinline__ float blk_sum256(float v, float* s8, int tid) {
    #pragma unroll
    for (int o = 16; o; o >>= 1) v += __shfl_xor_sync(0xffffffffu, v, o);
    if ((tid & 31) == 0) s8[tid >> 5] = v;
    __syncthreads();
    float r = s8[0]+s8[1]+s8[2]+s8[3]+s8[4]+s8[5]+s8[6]+s8[7];
    __syncthreads();
    return r;
}

// ---------------- kernel: LN reduce (block per token) ----------------
__global__ __launch_bounds__(256) void lnred_kernel(const float* __restrict__ ln_g,
                             const float* __restrict__ ln_b) {
    __shared__ float s8[8];
    int t = blockIdx.x;
    int tid = threadIdx.x;
    float v = g_bias2[tid];
    #pragma unroll
    for (int sl = 0; sl < NSL; sl++)
        v += g_part[((size_t)sl * NBC + t) * EE + tid];
    float mu = blk_sum256(v, s8, tid) * (1.f/EE);
    float d = v - mu;
    float var = blk_sum256(d*d, s8, tid) * (1.f/EE);
    g_ln[(size_t)t * EE + tid] = d * rsqrtf(var + LN_EPS) * ln_g[tid] + ln_b[tid];
}

// ---------------- kernel: FFN hidden ----------------
__global__ __launch_bounds__(256, 3) void ffn1_kernel(const float* __restrict__ b1) {
    __shared__ __align__(16) float s_ln[TOK][EE];
    __shared__ __align__(16) float s_acc[8][TOK][128];
    int t0 = blockIdx.x * TOK, slice = blockIdx.y;
    int tid = threadIdx.x;
    int jc = tid & 31, eg = tid >> 5;

    for (int i = tid; i < TOK*EE; i += 256)
        s_ln[i >> 8][i & 255] = g_ln[(size_t)(t0 + (i >> 8)) * EE + (i & 255)];
    __syncthreads();

    float4 a[TOK];
    #pragma unroll
    for (int tt = 0; tt < TOK; tt++) a[tt] = make_float4(0.f,0.f,0.f,0.f);

    const float4* Wp = ((const float4*)g_W1T) + (size_t)(eg*32) * 256 + slice*32 + jc;
    #pragma unroll 4
    for (int el = 0; el < 32; el++) {
        float4 w = Wp[(size_t)el * 256];
        int e = eg*32 + el;
        #pragma unroll
        for (int tt = 0; tt < TOK; tt++) {
            float lv = s_ln[tt][e];
            a[tt].x += w.x*lv; a[tt].y += w.y*lv;
            a[tt].z += w.z*lv; a[tt].w += w.w*lv;
        }
    }
    #pragma unroll
    for (int tt = 0; tt < TOK; tt++)
        *(float4*)&s_acc[eg][tt][jc*4] = a[tt];
    __syncthreads();

    #pragma unroll
    for (int r = 0; r < 4; r++) {
        int idx = r*256 + tid;
        int tt = idx >> 7, jj = idx & 127;
        float s = 0.f;
        #pragma unroll
        for (int eg2 = 0; eg2 < 8; eg2++) s += s_acc[eg2][tt][jj];
        g_hid[(size_t)(t0 + tt) * HID + slice*128 + jj] = fmaxf(s + b1[slice*128 + jj], 0.f);
    }
}

// ---------------- kernel: FFN out partial GEMM ----------------
__global__ __launch_bounds__(256, 3) void ffn2_kernel() {
    __shared__ __align__(16) float s_h[TOK][128];
    __shared__ __align__(16) float s_acc[4][TOK][EE];
    int t0 = blockIdx.x * TOK, slice = blockIdx.y;
    int tid = threadIdx.x;
    int fc = tid & 63, jg = tid >> 6;

    for (int i = tid; i < TOK*128; i += 256)
        s_h[i >> 7][i & 127] = g_hid[(size_t)(t0 + (i >> 7)) * HID + slice*128 + (i & 127)];
    __syncthreads();

    float4 a[TOK];
    #pragma unroll
    for (int tt = 0; tt < TOK; tt++) a[tt] = make_float4(0.f,0.f,0.f,0.f);

    const float4* Wp = ((const float4*)g_W2T) + (size_t)(slice*128 + jg*32) * 64 + fc;
    #pragma unroll 4
    for (int jl = 0; jl < 32; jl++) {
        float4 w = Wp[(size_t)jl * 64];
        int jj = jg*32 + jl;
        #pragma unroll
        for (int tt = 0; tt < TOK; tt++) {
            float hv = s_h[tt][jj];
            a[tt].x += w.x*hv; a[tt].y += w.y*hv;
            a[tt].z += w.z*hv; a[tt].w += w.w*hv;
        }
    }
    #pragma unroll
    for (int tt = 0; tt < TOK; tt++)
        *(float4*)&s_acc[jg][tt][fc*4] = a[tt];
    __syncthreads();

    int f = tid;
    #pragma unroll
    for (int tt = 0; tt < TOK; tt++) {
        float s = s_acc[0][tt][f] + s_acc[1][tt][f] + s_acc[2][tt][f] + s_acc[3][tt][f];
        g_part2[((size_t)slice * NBC + t0 + tt) * EE + f] = s;
    }
}

// ---------------- kernel: final reduce + residual + mask (block per token) ----------------
__global__ __launch_bounds__(256) void outred_kernel(const float* __restrict__ b2,
                              const int* __restrict__ real_cols,
                              float* __restrict__ out) {
    int t = blockIdx.x;
    int tid = threadIdx.x;
    int bidx = t >> 5, cidx = t & 31;
    bool valid = cidx < real_cols[bidx];
    float s = b2[tid] + g_ln[(size_t)t * EE + tid];
    #pragma unroll
    for (int sl = 0; sl < NSL; sl++)
        s += g_part2[((size_t)sl * NBC + t) * EE + tid];
    out[(size_t)t * EE + tid] = valid ? s : 0.f;
}

// ---------------- launch ----------------
extern "C" void kernel_launch(void* const* d_in, const int* in_sizes, int n_in,
                              void* d_out, int out_size) {
    const float* x         = (const float*)d_in[0];
    const int*   real_cols = (const int*)  d_in[1];
    const int*   real_rows = (const int*)  d_in[2];
    const float* cls       = (const float*)d_in[3];
    const float* w_qkv     = (const float*)d_in[4];
    const float* b_qkv     = (const float*)d_in[5];
    const float* w_out     = (const float*)d_in[6];
    const float* b_out     = (const float*)d_in[7];
    const float* ln_g      = (const float*)d_in[8];
    const float* ln_b      = (const float*)d_in[9];
    const float* w1        = (const float*)d_in[10];
    const float* b1        = (const float*)d_in[11];
    const float* w2        = (const float*)d_in[12];
    const float* b2        = (const float*)d_in[13];
    float* out = (float*)d_out;

    prep_kernel<<<1, 256>>>(cls, w_qkv, b_qkv, w_out, b_out);
    fused_kernel<<<NBC*NCH + 576, 256>>>(x, real_rows, cls, w_qkv, w_out, w1, w2);
    combine_kernel<<<NBC, 256>>>(real_rows);
    mha_part_kernel<<<dim3(NBC/TOK, NSL), 256>>>();
    lnred_kernel<<<NBC, 256>>>(ln_g, ln_b);
    ffn1_kernel<<<dim3(NBC/TOK, NSL), 256>>>(b1);
    ffn2_kernel<<<dim3(NBC/TOK, NSL), 256>>>();
    outred_kernel<<<NBC, 256>>>(b2, real_cols, out);
}

// round 6
// speedup vs baseline: 2.3626x; 2.3626x over previous
#include <cuda_runtime.h>
#include <cuda_bf16.h>
#include <cstdint>

#define EE    256
#define HH    4
#define DH    64
#define BB    8
#define CC    32
#define RR    255
#define SS    256
#define HID   1024
#define NBC   (BB*CC)
#define TOK   8
#define NSL   16           // j-split slices (64 j each)
#define LN_EPS 1e-5f

// ---------------- device scratch ----------------
__device__ float g_q0[EE];
__device__ float g_u[HH*EE];
__device__ float g_cb[HH];
__device__ float g_bias2[EE];
__device__ float g_M2T[HID*EE];      // [j][f]
__device__ float g_W1T[EE*HID];      // [e][j]
__device__ float g_W2T[HID*EE];      // [j][f]
__device__ float g_xbar[NBC*HID];
__device__ float g_ln[NBC*EE];
__device__ float g_hid[NBC*HID];
__device__ float g_part[NSL*NBC*EE];   // 4MB
__device__ float g_part2[NSL*NBC*EE];  // 4MB

// ---------------- kernel: q0 = W_q.cls + b_q (8 blocks, warp-cooperative) ----------------
__global__ __launch_bounds__(256) void prep1_kernel(const float* __restrict__ cls,
                              const float* __restrict__ w_qkv,
                              const float* __restrict__ b_qkv) {
    __shared__ float s_cls[EE];
    int tid = threadIdx.x, warp = tid >> 5, lane = tid & 31;
    if (tid < EE) s_cls[tid] = cls[tid];
    __syncthreads();
    #pragma unroll
    for (int q = 0; q < 4; q++) {
        int f = blockIdx.x * 32 + warp * 4 + q;
        const float* wr = w_qkv + (size_t)f * EE;
        float4 w0 = *(const float4*)(wr + lane*4);
        float4 w1 = *(const float4*)(wr + 128 + lane*4);
        float4 c0 = *(const float4*)(s_cls + lane*4);
        float4 c1 = *(const float4*)(s_cls + 128 + lane*4);
        float acc = w0.x*c0.x + w0.y*c0.y + w0.z*c0.z + w0.w*c0.w
                  + w1.x*c1.x + w1.y*c1.y + w1.z*c1.z + w1.w*c1.w;
        #pragma unroll
        for (int o = 16; o; o >>= 1) acc += __shfl_xor_sync(0xffffffffu, acc, o);
        if (lane == 0) g_q0[f] = acc + b_qkv[f];
    }
}

// ---------------- kernel: setup ----------------
// [0,64): M2T tiles | [64,320): W1 transpose | [320,576): W2 transpose
// [576,584): u | 584: cb | [585,593): bias2
__global__ __launch_bounds__(256) void setup_kernel(const float* __restrict__ w_qkv,
                              const float* __restrict__ b_qkv,
                              const float* __restrict__ w_out,
                              const float* __restrict__ b_out,
                              const float* __restrict__ w1,
                              const float* __restrict__ w2) {
    int bi = blockIdx.x;
    int tid = threadIdx.x;

    if (bi < 64) {
        __shared__ float sa[64][64];
        __shared__ float sb[64][65];
        int h = bi >> 4, e0 = ((bi >> 2) & 3) * 64, f0 = (bi & 3) * 64;
        for (int i = tid; i < 4096; i += 256) {
            int d = i >> 6, el = i & 63;
            sa[d][el] = w_qkv[(size_t)(2*EE + h*64 + d) * EE + e0 + el];
        }
        for (int i = tid; i < 4096; i += 256) {
            int fl = i >> 6, d = i & 63;
            sb[fl][d] = w_out[(size_t)(f0 + fl) * EE + h*64 + d];
        }
        __syncthreads();
        int tx = tid & 15, ty = tid >> 4;
        float acc[4][4] = {};
        #pragma unroll 4
        for (int d = 0; d < 64; d++) {
            float av[4], bv[4];
            #pragma unroll
            for (int i = 0; i < 4; i++) av[i] = sa[d][ty*4 + i];
            #pragma unroll
            for (int i = 0; i < 4; i++) bv[i] = sb[tx*4 + i][d];
            #pragma unroll
            for (int i = 0; i < 4; i++)
                #pragma unroll
                for (int j = 0; j < 4; j++) acc[i][j] += av[i] * bv[j];
        }
        #pragma unroll
        for (int i = 0; i < 4; i++)
            *(float4*)&g_M2T[(size_t)(h*256 + e0 + ty*4 + i) * EE + f0 + tx*4] = *(float4*)acc[i];
        return;
    }
    if (bi < 576) {
        __shared__ float s[32][33];
        int a = bi - 64;
        const float* src; float* dst; int rows, cols, bx, by;
        if (a < 256) {             // W1 [1024][256] -> W1T
            src = w1; dst = g_W1T; rows = HID; cols = EE;
            bx = (a & 7) * 32; by = (a >> 3) * 32;
        } else {                   // W2 [256][1024] -> W2T
            a -= 256;
            src = w2; dst = g_W2T; rows = EE; cols = HID;
            bx = (a & 31) * 32; by = (a >> 5) * 32;
        }
        int tx = tid & 31, ty = tid >> 5;
        #pragma unroll
        for (int r = 0; r < 4; r++)
            s[ty + r*8][tx] = src[(size_t)(by + ty + r*8) * cols + bx + tx];
        __syncthreads();
        #pragma unroll
        for (int r = 0; r < 4; r++)
            dst[(size_t)(bx + ty + r*8) * rows + by + tx] = s[tx][ty + r*8];
        return;
    }
    if (bi < 584) {
        // ---- u[h][e] = 0.125 * sum_d q0[h*64+d] * W_k[h*64+d][e] ----
        __shared__ float s_q[DH];
        __shared__ float s_p[2][128];
        int k = bi - 576;
        int h = k >> 1, e0 = (k & 1) * 128;
        if (tid < DH) s_q[tid] = g_q0[h*DH + tid];
        __syncthreads();
        int dg = tid >> 7, e = e0 + (tid & 127);
        float acc = 0.f;
        #pragma unroll 8
        for (int i = 0; i < 32; i++) {
            int d = dg*32 + i;
            acc += s_q[d] * w_qkv[(size_t)(EE + h*DH + d) * EE + e];
        }
        s_p[dg][tid & 127] = acc;
        __syncthreads();
        if (tid < 128)
            g_u[h*EE + e0 + tid] = 0.125f * (s_p[0][tid] + s_p[1][tid]);
        return;
    }
    if (bi == 584) {
        // ---- cb[h] = 0.125 * q0[h].b_k[h] ----
        __shared__ float s_w[8];
        int h = tid >> 6, d = tid & 63;
        float v = g_q0[h*DH + d] * b_qkv[EE + h*DH + d];
        #pragma unroll
        for (int o = 16; o; o >>= 1) v += __shfl_xor_sync(0xffffffffu, v, o);
        if ((tid & 31) == 0) s_w[tid >> 5] = v;
        __syncthreads();
        if (tid < HH) g_cb[tid] = 0.125f * (s_w[2*tid] + s_w[2*tid + 1]);
        return;
    }
    {
        // ---- bias2[f] = W_out[f,:].b_v + b_out[f] ----
        __shared__ float s_bv[EE];
        int base = (bi - 585) * 32;
        int warp = tid >> 5, lane = tid & 31;
        if (tid < EE) s_bv[tid] = b_qkv[2*EE + tid];
        __syncthreads();
        #pragma unroll
        for (int q = 0; q < 4; q++) {
            int f = base + warp * 4 + q;
            const float* wr = w_out + (size_t)f * EE;
            float4 w0 = *(const float4*)(wr + lane*4);
            float4 w1 = *(const float4*)(wr + 128 + lane*4);
            float4 c0 = *(const float4*)(s_bv + lane*4);
            float4 c1 = *(const float4*)(s_bv + 128 + lane*4);
            float acc = w0.x*c0.x + w0.y*c0.y + w0.z*c0.z + w0.w*c0.w
                      + w1.x*c1.x + w1.y*c1.y + w1.z*c1.z + w1.w*c1.w;
            #pragma unroll
            for (int o = 16; o; o >>= 1) acc += __shfl_xor_sync(0xffffffffu, acc, o);
            if (lane == 0) g_bias2[f] = acc + b_out[f];
        }
    }
}

// ---------------- kernel: attention -> xbar ----------------
__global__ __launch_bounds__(1024) void attn_kernel(const float* __restrict__ x,
                            const int* __restrict__ real_rows,
                            const float* __restrict__ cls) {
    __shared__ __align__(16) float s_u[HH*EE];
    __shared__ __align__(16) float s_sc[HH][SS];
    __shared__ __align__(16) float s_cls[EE];
    __shared__ __align__(16) float s_part[8][HH][EE];
    __shared__ float s_cb[HH];

    int bc  = blockIdx.x;
    int b   = bc >> 5;
    int tid = threadIdx.x;
    int warp = tid >> 5, lane = tid & 31;

    s_u[tid] = g_u[tid];
    if (tid < EE) s_cls[tid] = cls[tid];
    if (tid < HH) s_cb[tid] = g_cb[tid];
    __syncthreads();

    int nk = real_rows[b] + 1;
    const float* xbase = x + (size_t)bc * RR * EE;

    // ---- phase A: scores, warp per position, 2-deep pipeline ----
    {
        int pos = warp;
        bool have = pos < nk;
        float4 v0, v1;
        if (have) {
            const float* row = (pos == 0) ? s_cls : (xbase + (size_t)(pos - 1) * EE);
            v0 = *(const float4*)(row + lane*4);
            v1 = *(const float4*)(row + 128 + lane*4);
        }
        while (have) {
            int npos = pos + 32;
            bool nh = npos < nk;
            float4 n0, n1;
            if (nh) {
                const float* nrow = xbase + (size_t)(npos - 1) * EE;
                n0 = *(const float4*)(nrow + lane*4);
                n1 = *(const float4*)(nrow + 128 + lane*4);
            }
            float acc[HH];
            #pragma unroll
            for (int h = 0; h < HH; h++) {
                float4 u0 = *(const float4*)(s_u + h*EE + lane*4);
                float4 u1 = *(const float4*)(s_u + h*EE + 128 + lane*4);
                acc[h] = v0.x*u0.x + v0.y*u0.y + v0.z*u0.z + v0.w*u0.w
                       + v1.x*u1.x + v1.y*u1.y + v1.z*u1.z + v1.w*u1.w;
            }
            #pragma unroll
            for (int o = 16; o; o >>= 1) {
                #pragma unroll
                for (int h = 0; h < HH; h++)
                    acc[h] += __shfl_xor_sync(0xffffffffu, acc[h], o);
            }
            if (lane == 0) {
                #pragma unroll
                for (int h = 0; h < HH; h++) s_sc[h][pos] = acc[h] + s_cb[h];
            }
            pos = npos; have = nh; v0 = n0; v1 = n1;
        }
    }
    __syncthreads();

    // ---- phase B: softmax per head ----
    if (warp < HH) {
        int h = warp;
        float m = -3.0e38f;
        for (int p = lane; p < nk; p += 32) m = fmaxf(m, s_sc[h][p]);
        #pragma unroll
        for (int o = 16; o; o >>= 1) m = fmaxf(m, __shfl_xor_sync(0xffffffffu, m, o));
        float sum = 0.f;
        for (int p = lane; p < nk; p += 32) {
            float ev = __expf(s_sc[h][p] - m);
            s_sc[h][p] = ev;
            sum += ev;
        }
        #pragma unroll
        for (int o = 16; o; o >>= 1) sum += __shfl_xor_sync(0xffffffffu, sum, o);
        float inv = 1.f / sum;
        for (int p = lane; p < nk; p += 32) s_sc[h][p] *= inv;
    }
    __syncthreads();

    // ---- phase C: 8-way position split, float2, unroll 8 ----
    int pg = tid >> 7, ec = tid & 127;
    float2 a[HH];
    #pragma unroll
    for (int h = 0; h < HH; h++) a[h] = make_float2(0.f, 0.f);
    #pragma unroll 8
    for (int pos = pg; pos < nk; pos += 8) {
        float2 xv = (pos == 0) ? *(const float2*)(s_cls + ec*2)
                               : *(const float2*)(xbase + (size_t)(pos - 1) * EE + ec*2);
        #pragma unroll
        for (int h = 0; h < HH; h++) {
            float w = s_sc[h][pos];
            a[h].x += w * xv.x; a[h].y += w * xv.y;
        }
    }
    #pragma unroll
    for (int h = 0; h < HH; h++)
        *(float2*)&s_part[pg][h][ec*2] = a[h];
    __syncthreads();

    int h2 = tid >> 8, e2 = tid & 255;
    float s = 0.f;
    #pragma unroll
    for (int g = 0; g < 8; g++) s += s_part[g][h2][e2];
    g_xbar[(size_t)bc * HID + tid] = s;
}

// ---------------- kernel: mha partial GEMM (grid 32x16) ----------------
__global__ __launch_bounds__(256, 3) void mha_part_kernel() {
    __shared__ __align__(16) float s_xb[TOK][64];
    __shared__ __align__(16) float s_acc[4][TOK][260];
    int t0 = blockIdx.x * TOK, slice = blockIdx.y;
    int tid = threadIdx.x;
    int fc = tid & 63, jg = tid >> 6;

    for (int i = tid; i < TOK*64; i += 256)
        s_xb[i >> 6][i & 63] = g_xbar[(size_t)(t0 + (i >> 6)) * HID + slice*64 + (i & 63)];
    __syncthreads();

    float4 a[TOK];
    #pragma unroll
    for (int tt = 0; tt < TOK; tt++) a[tt] = make_float4(0.f,0.f,0.f,0.f);

    const float4* Mp = ((const float4*)g_M2T) + (size_t)(slice*64 + jg*16) * 64 + fc;
    #pragma unroll 4
    for (int jl = 0; jl < 16; jl++) {
        float4 m = Mp[(size_t)jl * 64];
        int jj = jg*16 + jl;
        #pragma unroll
        for (int tt = 0; tt < TOK; tt++) {
            float xv = s_xb[tt][jj];
            a[tt].x += m.x*xv; a[tt].y += m.y*xv;
            a[tt].z += m.z*xv; a[tt].w += m.w*xv;
        }
    }
    #pragma unroll
    for (int tt = 0; tt < TOK; tt++)
        *(float4*)&s_acc[jg][tt][fc*4] = a[tt];
    __syncthreads();

    int f = tid;
    #pragma unroll
    for (int tt = 0; tt < TOK; tt++) {
        float s = s_acc[0][tt][f] + s_acc[1][tt][f] + s_acc[2][tt][f] + s_acc[3][tt][f];
        g_part[((size_t)slice * NBC + t0 + tt) * EE + f] = s;
    }
}

// ---------------- block reduce ----------------
__device__ __forceinline__ float blk_sum256(float v, float* s8, int tid) {
    #pragma unroll
    for (int o = 16; o; o >>= 1) v += __shfl_xor_sync(0xffffffffu, v, o);
    if ((tid & 31) == 0) s8[tid >> 5] = v;
    __syncthreads();
    float r = s8[0]+s8[1]+s8[2]+s8[3]+s8[4]+s8[5]+s8[6]+s8[7];
    __syncthreads();
    return r;
}

// ---------------- kernel: LN reduce (block per token) ----------------
__global__ __launch_bounds__(256) void lnred_kernel(const float* __restrict__ ln_g,
                             const float* __restrict__ ln_b) {
    __shared__ float s8[8];
    int t = blockIdx.x;
    int tid = threadIdx.x;
    float v = g_bias2[tid];
    #pragma unroll
    for (int sl = 0; sl < NSL; sl++)
        v += g_part[((size_t)sl * NBC + t) * EE + tid];
    float mu = blk_sum256(v, s8, tid) * (1.f/EE);
    float d = v - mu;
    float var = blk_sum256(d*d, s8, tid) * (1.f/EE);
    g_ln[(size_t)t * EE + tid] = d * rsqrtf(var + LN_EPS) * ln_g[tid] + ln_b[tid];
}

// ---------------- kernel: FFN hidden (grid 32x16) ----------------
__global__ __launch_bounds__(256, 3) void ffn1_kernel(const float* __restrict__ b1) {
    __shared__ __align__(16) float s_ln[TOK][EE];
    __shared__ __align__(16) float s_acc[16][TOK][68];
    int t0 = blockIdx.x * TOK, slice = blockIdx.y;
    int tid = threadIdx.x;
    int jc = tid & 15, eg = tid >> 4;

    for (int i = tid; i < TOK*EE; i += 256)
        s_ln[i >> 8][i & 255] = g_ln[(size_t)(t0 + (i >> 8)) * EE + (i & 255)];
    __syncthreads();

    float4 a[TOK];
    #pragma unroll
    for (int tt = 0; tt < TOK; tt++) a[tt] = make_float4(0.f,0.f,0.f,0.f);

    // W1T row e = 1024 floats = 256 float4; this block's quads: slice*16 + jc
    const float4* Wp = ((const float4*)g_W1T) + (size_t)(eg*16) * 256 + slice*16 + jc;
    #pragma unroll 4
    for (int el = 0; el < 16; el++) {
        float4 w = Wp[(size_t)el * 256];
        int e = eg*16 + el;
        #pragma unroll
        for (int tt = 0; tt < TOK; tt++) {
            float lv = s_ln[tt][e];
            a[tt].x += w.x*lv; a[tt].y += w.y*lv;
            a[tt].z += w.z*lv; a[tt].w += w.w*lv;
        }
    }
    #pragma unroll
    for (int tt = 0; tt < TOK; tt++)
        *(float4*)&s_acc[eg][tt][jc*4] = a[tt];
    __syncthreads();

    #pragma unroll
    for (int r = 0; r < 2; r++) {
        int idx = r*256 + tid;           // [tt][jj] over 8x64
        int tt = idx >> 6, jj = idx & 63;
        float s = 0.f;
        #pragma unroll
        for (int g = 0; g < 16; g++) s += s_acc[g][tt][jj];
        g_hid[(size_t)(t0 + tt) * HID + slice*64 + jj] = fmaxf(s + b1[slice*64 + jj], 0.f);
    }
}

// ---------------- kernel: FFN out partial GEMM (grid 32x16) ----------------
__global__ __launch_bounds__(256, 3) void ffn2_kernel() {
    __shared__ __align__(16) float s_h[TOK][64];
    __shared__ __align__(16) float s_acc[4][TOK][260];
    int t0 = blockIdx.x * TOK, slice = blockIdx.y;
    int tid = threadIdx.x;
    int fc = tid & 63, jg = tid >> 6;

    for (int i = tid; i < TOK*64; i += 256)
        s_h[i >> 6][i & 63] = g_hid[(size_t)(t0 + (i >> 6)) * HID + slice*64 + (i & 63)];
    __syncthreads();

    float4 a[TOK];
    #pragma unroll
    for (int tt = 0; tt < TOK; tt++) a[tt] = make_float4(0.f,0.f,0.f,0.f);

    const float4* Wp = ((const float4*)g_W2T) + (size_t)(slice*64 + jg*16) * 64 + fc;
    #pragma unroll 4
    for (int jl = 0; jl < 16; jl++) {
        float4 w = Wp[(size_t)jl * 64];
        int jj = jg*16 + jl;
        #pragma unroll
        for (int tt = 0; tt < TOK; tt++) {
            float hv = s_h[tt][jj];
            a[tt].x += w.x*hv; a[tt].y += w.y*hv;
            a[tt].z += w.z*hv; a[tt].w += w.w*hv;
        }
    }
    #pragma unroll
    for (int tt = 0; tt < TOK; tt++)
        *(float4*)&s_acc[jg][tt][fc*4] = a[tt];
    __syncthreads();

    int f = tid;
    #pragma unroll
    for (int tt = 0; tt < TOK; tt++) {
        float s = s_acc[0][tt][f] + s_acc[1][tt][f] + s_acc[2][tt][f] + s_acc[3][tt][f];
        g_part2[((size_t)slice * NBC + t0 + tt) * EE + f] = s;
    }
}

// ---------------- kernel: final reduce + residual + mask ----------------
__global__ __launch_bounds__(256) void outred_kernel(const float* __restrict__ b2,
                              const int* __restrict__ real_cols,
                              float* __restrict__ out) {
    int t = blockIdx.x;
    int tid = threadIdx.x;
    int bidx = t >> 5, cidx = t & 31;
    bool valid = cidx < real_cols[bidx];
    float s = b2[tid] + g_ln[(size_t)t * EE + tid];
    #pragma unroll
    for (int sl = 0; sl < NSL; sl++)
        s += g_part2[((size_t)sl * NBC + t) * EE + tid];
    out[(size_t)t * EE + tid] = valid ? s : 0.f;
}

// ---------------- launch ----------------
extern "C" void kernel_launch(void* const* d_in, const int* in_sizes, int n_in,
                              void* d_out, int out_size) {
    const float* x         = (const float*)d_in[0];
    const int*   real_cols = (const int*)  d_in[1];
    const int*   real_rows = (const int*)  d_in[2];
    const float* cls       = (const float*)d_in[3];
    const float* w_qkv     = (const float*)d_in[4];
    const float* b_qkv     = (const float*)d_in[5];
    const float* w_out     = (const float*)d_in[6];
    const float* b_out     = (const float*)d_in[7];
    const float* ln_g      = (const float*)d_in[8];
    const float* ln_b      = (const float*)d_in[9];
    const float* w1        = (const float*)d_in[10];
    const float* b1        = (const float*)d_in[11];
    const float* w2        = (const float*)d_in[12];
    const float* b2        = (const float*)d_in[13];
    float* out = (float*)d_out;

    prep1_kernel<<<8, 256>>>(cls, w_qkv, b_qkv);
    setup_kernel<<<593, 256>>>(w_qkv, b_qkv, w_out, b_out, w1, w2);
    attn_kernel<<<NBC, 1024>>>(x, real_rows, cls);
    mha_part_kernel<<<dim3(NBC/TOK, NSL), 256>>>();
    lnred_kernel<<<NBC, 256>>>(ln_g, ln_b);
    ffn1_kernel<<<dim3(NBC/TOK, NSL), 256>>>(b1);
    ffn2_kernel<<<dim3(NBC/TOK, NSL), 256>>>();
    outred_kernel<<<NBC, 256>>>(b2, real_cols, out);
}

// round 7
// speedup vs baseline: 2.7740x; 1.1742x over previous
#include <cuda_runtime.h>
#include <cuda_bf16.h>
#include <cstdint>

#define EE    256
#define HH    4
#define DH    64
#define BB    8
#define CC    32
#define RR    255
#define SS    256
#define HID   1024
#define NBC   (BB*CC)
#define TOK   8
#define NSL   16           // j-split slices (64 j each)
#define LN_EPS 1e-5f

// ---------------- device scratch ----------------
__device__ __align__(16) float g_q0[EE];
__device__ __align__(16) float g_u[HH*EE];
__device__ __align__(16) float g_cb[HH];
__device__ __align__(16) float g_bias2[EE];
__device__ __align__(16) float g_M2T[HID*EE];      // [j][f]
__device__ __align__(16) float g_W1T[EE*HID];      // [e][j]
__device__ __align__(16) float g_W2T[HID*EE];      // [j][f]
__device__ __align__(16) float g_xbar[NBC*HID];
__device__ __align__(16) float g_ln[NBC*EE];
__device__ __align__(16) float g_hid[NBC*HID];
__device__ __align__(16) float g_part[NSL*NBC*EE];   // 4MB
__device__ __align__(16) float g_part2[NSL*NBC*EE];  // 4MB

// ---------------- cp.async helpers ----------------
__device__ __forceinline__ void cp_async16(float* sdst, const float4* gsrc) {
    unsigned sa = (unsigned)__cvta_generic_to_shared(sdst);
    asm volatile("cp.async.ca.shared.global [%0], [%1], 16;" :: "r"(sa), "l"(gsrc));
}
__device__ __forceinline__ void cp_commit() { asm volatile("cp.async.commit_group;"); }
__device__ __forceinline__ void cp_wait1()  { asm volatile("cp.async.wait_group 1;"); }
__device__ __forceinline__ void cp_wait0()  { asm volatile("cp.async.wait_group 0;"); }

// 8-token FMA: acc[tt] (float4 over 4 outputs) += v[tt] * m
#define ACC8(m, tA, tB) do { \
    a[0].x += (m).x*(tA).x; a[0].y += (m).y*(tA).x; a[0].z += (m).z*(tA).x; a[0].w += (m).w*(tA).x; \
    a[1].x += (m).x*(tA).y; a[1].y += (m).y*(tA).y; a[1].z += (m).z*(tA).y; a[1].w += (m).w*(tA).y; \
    a[2].x += (m).x*(tA).z; a[2].y += (m).y*(tA).z; a[2].z += (m).z*(tA).z; a[2].w += (m).w*(tA).z; \
    a[3].x += (m).x*(tA).w; a[3].y += (m).y*(tA).w; a[3].z += (m).z*(tA).w; a[3].w += (m).w*(tA).w; \
    a[4].x += (m).x*(tB).x; a[4].y += (m).y*(tB).x; a[4].z += (m).z*(tB).x; a[4].w += (m).w*(tB).x; \
    a[5].x += (m).x*(tB).y; a[5].y += (m).y*(tB).y; a[5].z += (m).z*(tB).y; a[5].w += (m).w*(tB).y; \
    a[6].x += (m).x*(tB).z; a[6].y += (m).y*(tB).z; a[6].z += (m).z*(tB).z; a[6].w += (m).w*(tB).z; \
    a[7].x += (m).x*(tB).w; a[7].y += (m).y*(tB).w; a[7].z += (m).z*(tB).w; a[7].w += (m).w*(tB).w; \
} while(0)

// ---------------- kernel: q0 = W_q.cls + b_q ----------------
__global__ __launch_bounds__(256) void prep1_kernel(const float* __restrict__ cls,
                              const float* __restrict__ w_qkv,
                              const float* __restrict__ b_qkv) {
    __shared__ float s_cls[EE];
    int tid = threadIdx.x, warp = tid >> 5, lane = tid & 31;
    if (tid < EE) s_cls[tid] = cls[tid];
    __syncthreads();
    #pragma unroll
    for (int q = 0; q < 4; q++) {
        int f = blockIdx.x * 32 + warp * 4 + q;
        const float* wr = w_qkv + (size_t)f * EE;
        float4 w0 = *(const float4*)(wr + lane*4);
        float4 w1 = *(const float4*)(wr + 128 + lane*4);
        float4 c0 = *(const float4*)(s_cls + lane*4);
        float4 c1 = *(const float4*)(s_cls + 128 + lane*4);
        float acc = w0.x*c0.x + w0.y*c0.y + w0.z*c0.z + w0.w*c0.w
                  + w1.x*c1.x + w1.y*c1.y + w1.z*c1.z + w1.w*c1.w;
        #pragma unroll
        for (int o = 16; o; o >>= 1) acc += __shfl_xor_sync(0xffffffffu, acc, o);
        if (lane == 0) g_q0[f] = acc + b_qkv[f];
    }
}

// ---------------- kernel: setup ----------------
__global__ __launch_bounds__(256) void setup_kernel(const float* __restrict__ w_qkv,
                              const float* __restrict__ b_qkv,
                              const float* __restrict__ w_out,
                              const float* __restrict__ b_out,
                              const float* __restrict__ w1,
                              const float* __restrict__ w2) {
    int bi = blockIdx.x;
    int tid = threadIdx.x;

    if (bi < 64) {
        __shared__ float sa[64][64];
        __shared__ float sb[64][65];
        int h = bi >> 4, e0 = ((bi >> 2) & 3) * 64, f0 = (bi & 3) * 64;
        for (int i = tid; i < 4096; i += 256) {
            int d = i >> 6, el = i & 63;
            sa[d][el] = w_qkv[(size_t)(2*EE + h*64 + d) * EE + e0 + el];
        }
        for (int i = tid; i < 4096; i += 256) {
            int fl = i >> 6, d = i & 63;
            sb[fl][d] = w_out[(size_t)(f0 + fl) * EE + h*64 + d];
        }
        __syncthreads();
        int tx = tid & 15, ty = tid >> 4;
        float acc[4][4] = {};
        #pragma unroll 4
        for (int d = 0; d < 64; d++) {
            float av[4], bv[4];
            #pragma unroll
            for (int i = 0; i < 4; i++) av[i] = sa[d][ty*4 + i];
            #pragma unroll
            for (int i = 0; i < 4; i++) bv[i] = sb[tx*4 + i][d];
            #pragma unroll
            for (int i = 0; i < 4; i++)
                #pragma unroll
                for (int j = 0; j < 4; j++) acc[i][j] += av[i] * bv[j];
        }
        #pragma unroll
        for (int i = 0; i < 4; i++)
            *(float4*)&g_M2T[(size_t)(h*256 + e0 + ty*4 + i) * EE + f0 + tx*4] = *(float4*)acc[i];
        return;
    }
    if (bi < 576) {
        __shared__ float s[32][33];
        int a = bi - 64;
        const float* src; float* dst; int rows, cols, bx, by;
        if (a < 256) {
            src = w1; dst = g_W1T; rows = HID; cols = EE;
            bx = (a & 7) * 32; by = (a >> 3) * 32;
        } else {
            a -= 256;
            src = w2; dst = g_W2T; rows = EE; cols = HID;
            bx = (a & 31) * 32; by = (a >> 5) * 32;
        }
        int tx = tid & 31, ty = tid >> 5;
        #pragma unroll
        for (int r = 0; r < 4; r++)
            s[ty + r*8][tx] = src[(size_t)(by + ty + r*8) * cols + bx + tx];
        __syncthreads();
        #pragma unroll
        for (int r = 0; r < 4; r++)
            dst[(size_t)(bx + ty + r*8) * rows + by + tx] = s[tx][ty + r*8];
        return;
    }
    if (bi < 584) {
        __shared__ float s_q[DH];
        __shared__ float s_p[2][128];
        int k = bi - 576;
        int h = k >> 1, e0 = (k & 1) * 128;
        if (tid < DH) s_q[tid] = g_q0[h*DH + tid];
        __syncthreads();
        int dg = tid >> 7, e = e0 + (tid & 127);
        float acc = 0.f;
        #pragma unroll 8
        for (int i = 0; i < 32; i++) {
            int d = dg*32 + i;
            acc += s_q[d] * w_qkv[(size_t)(EE + h*DH + d) * EE + e];
        }
        s_p[dg][tid & 127] = acc;
        __syncthreads();
        if (tid < 128)
            g_u[h*EE + e0 + tid] = 0.125f * (s_p[0][tid] + s_p[1][tid]);
        return;
    }
    if (bi == 584) {
        __shared__ float s_w[8];
        int h = tid >> 6, d = tid & 63;
        float v = g_q0[h*DH + d] * b_qkv[EE + h*DH + d];
        #pragma unroll
        for (int o = 16; o; o >>= 1) v += __shfl_xor_sync(0xffffffffu, v, o);
        if ((tid & 31) == 0) s_w[tid >> 5] = v;
        __syncthreads();
        if (tid < HH) g_cb[tid] = 0.125f * (s_w[2*tid] + s_w[2*tid + 1]);
        return;
    }
    {
        __shared__ float s_bv[EE];
        int base = (bi - 585) * 32;
        int warp = tid >> 5, lane = tid & 31;
        if (tid < EE) s_bv[tid] = b_qkv[2*EE + tid];
        __syncthreads();
        #pragma unroll
        for (int q = 0; q < 4; q++) {
            int f = base + warp * 4 + q;
            const float* wr = w_out + (size_t)f * EE;
            float4 w0 = *(const float4*)(wr + lane*4);
            float4 w1 = *(const float4*)(wr + 128 + lane*4);
            float4 c0 = *(const float4*)(s_bv + lane*4);
            float4 c1 = *(const float4*)(s_bv + 128 + lane*4);
            float acc = w0.x*c0.x + w0.y*c0.y + w0.z*c0.z + w0.w*c0.w
                      + w1.x*c1.x + w1.y*c1.y + w1.z*c1.z + w1.w*c1.w;
            #pragma unroll
            for (int o = 16; o; o >>= 1) acc += __shfl_xor_sync(0xffffffffu, acc, o);
            if (lane == 0) g_bias2[f] = acc + b_out[f];
        }
    }
}

// ---------------- kernel: attention -> xbar ----------------
__global__ __launch_bounds__(1024) void attn_kernel(const float* __restrict__ x,
                            const int* __restrict__ real_rows,
                            const float* __restrict__ cls) {
    __shared__ __align__(16) float s_u[HH*EE];
    __shared__ __align__(16) float s_sc[HH][SS];
    __shared__ __align__(16) float s_cls[EE];
    __shared__ __align__(16) float s_part[8][HH][EE];
    __shared__ float s_cb[HH];

    int bc  = blockIdx.x;
    int b   = bc >> 5;
    int tid = threadIdx.x;
    int warp = tid >> 5, lane = tid & 31;

    s_u[tid] = g_u[tid];
    if (tid < EE) s_cls[tid] = cls[tid];
    if (tid < HH) s_cb[tid] = g_cb[tid];
    __syncthreads();

    int nk = real_rows[b] + 1;
    const float* xbase = x + (size_t)bc * RR * EE;

    {
        int pos = warp;
        bool have = pos < nk;
        float4 v0, v1;
        if (have) {
            const float* row = (pos == 0) ? s_cls : (xbase + (size_t)(pos - 1) * EE);
            v0 = *(const float4*)(row + lane*4);
            v1 = *(const float4*)(row + 128 + lane*4);
        }
        while (have) {
            int npos = pos + 32;
            bool nh = npos < nk;
            float4 n0, n1;
            if (nh) {
                const float* nrow = xbase + (size_t)(npos - 1) * EE;
                n0 = *(const float4*)(nrow + lane*4);
                n1 = *(const float4*)(nrow + 128 + lane*4);
            }
            float acc[HH];
            #pragma unroll
            for (int h = 0; h < HH; h++) {
                float4 u0 = *(const float4*)(s_u + h*EE + lane*4);
                float4 u1 = *(const float4*)(s_u + h*EE + 128 + lane*4);
                acc[h] = v0.x*u0.x + v0.y*u0.y + v0.z*u0.z + v0.w*u0.w
                       + v1.x*u1.x + v1.y*u1.y + v1.z*u1.z + v1.w*u1.w;
            }
            #pragma unroll
            for (int o = 16; o; o >>= 1) {
                #pragma unroll
                for (int h = 0; h < HH; h++)
                    acc[h] += __shfl_xor_sync(0xffffffffu, acc[h], o);
            }
            if (lane == 0) {
                #pragma unroll
                for (int h = 0; h < HH; h++) s_sc[h][pos] = acc[h] + s_cb[h];
            }
            pos = npos; have = nh; v0 = n0; v1 = n1;
        }
    }
    __syncthreads();

    if (warp < HH) {
        int h = warp;
        float m = -3.0e38f;
        for (int p = lane; p < nk; p += 32) m = fmaxf(m, s_sc[h][p]);
        #pragma unroll
        for (int o = 16; o; o >>= 1) m = fmaxf(m, __shfl_xor_sync(0xffffffffu, m, o));
        float sum = 0.f;
        for (int p = lane; p < nk; p += 32) {
            float ev = __expf(s_sc[h][p] - m);
            s_sc[h][p] = ev;
            sum += ev;
        }
        #pragma unroll
        for (int o = 16; o; o >>= 1) sum += __shfl_xor_sync(0xffffffffu, sum, o);
        float inv = 1.f / sum;
        for (int p = lane; p < nk; p += 32) s_sc[h][p] *= inv;
    }
    __syncthreads();

    int pg = tid >> 7, ec = tid & 127;
    float2 a[HH];
    #pragma unroll
    for (int h = 0; h < HH; h++) a[h] = make_float2(0.f, 0.f);
    #pragma unroll 8
    for (int pos = pg; pos < nk; pos += 8) {
        float2 xv = (pos == 0) ? *(const float2*)(s_cls + ec*2)
                               : *(const float2*)(xbase + (size_t)(pos - 1) * EE + ec*2);
        #pragma unroll
        for (int h = 0; h < HH; h++) {
            float w = s_sc[h][pos];
            a[h].x += w * xv.x; a[h].y += w * xv.y;
        }
    }
    #pragma unroll
    for (int h = 0; h < HH; h++)
        *(float2*)&s_part[pg][h][ec*2] = a[h];
    __syncthreads();

    int h2 = tid >> 8, e2 = tid & 255;
    float s = 0.f;
    #pragma unroll
    for (int g = 0; g < 8; g++) s += s_part[g][h2][e2];
    g_xbar[(size_t)bc * HID + tid] = s;
}

// ---------------- kernel: mha partial GEMM (cp.async double-buffered) ----------------
__global__ __launch_bounds__(256) void mha_part_kernel() {
    __shared__ __align__(16) float s_xbT[64][8];     // 2KB, [j][token]
    __shared__ __align__(16) float s_buf[8320];      // union: weights 2x4096 | s_acc[4][8][260]
    int t0 = blockIdx.x * TOK, slice = blockIdx.y;
    int tid = threadIdx.x;
    int fc = tid & 63, jg = tid >> 6;

    const float4* Wg = (const float4*)g_M2T + (size_t)(slice*64) * 64; // row j: 64 float4

    // prefetch chunk 0 (j rows 0..15 of tile)
    #pragma unroll
    for (int r = 0; r < 4; r++) {
        int idx = r*256 + tid;
        cp_async16(&s_buf[idx*4], Wg + idx);
    }
    cp_commit();

    // load xbar transposed: s_xbT[j][t]
    #pragma unroll
    for (int r = 0; r < 2; r++) {
        int idx = r*256 + tid;
        int t = idx >> 6, j = idx & 63;
        s_xbT[j][t] = g_xbar[(size_t)(t0 + t) * HID + slice*64 + j];
    }

    float4 a[TOK];
    #pragma unroll
    for (int tt = 0; tt < TOK; tt++) a[tt] = make_float4(0.f,0.f,0.f,0.f);

    #pragma unroll
    for (int c = 0; c < 4; c++) {
        if (c < 3) {
            const float4* src = Wg + (c+1)*1024;
            float* dst = &s_buf[((c+1)&1)*4096];
            #pragma unroll
            for (int r = 0; r < 4; r++) {
                int idx = r*256 + tid;
                cp_async16(dst + idx*4, src + idx);
            }
            cp_commit();
            cp_wait1();
        } else {
            cp_wait0();
        }
        __syncthreads();
        const float* wb = &s_buf[(c&1)*4096];
        #pragma unroll
        for (int jl = 0; jl < 4; jl++) {
            int j = jg*4 + jl;
            float4 m  = *(const float4*)&wb[(j*64 + fc)*4];
            float4 tA = *(const float4*)&s_xbT[c*16 + j][0];
            float4 tB = *(const float4*)&s_xbT[c*16 + j][4];
            ACC8(m, tA, tB);
        }
        __syncthreads();
    }

    // reduce 4 jg groups via overlay s_acc[4][8][260]
    float* s_acc = s_buf;
    #pragma unroll
    for (int tt = 0; tt < TOK; tt++)
        *(float4*)&s_acc[(jg*TOK + tt)*260 + fc*4] = a[tt];
    __syncthreads();
    int f = tid;
    #pragma unroll
    for (int tt = 0; tt < TOK; tt++) {
        float s = s_acc[(0*TOK+tt)*260 + f] + s_acc[(1*TOK+tt)*260 + f]
                + s_acc[(2*TOK+tt)*260 + f] + s_acc[(3*TOK+tt)*260 + f];
        g_part[((size_t)slice * NBC + t0 + tt) * EE + f] = s;
    }
}

// ---------------- block reduce ----------------
__device__ __forceinline__ float blk_sum256(float v, float* s8, int tid) {
    #pragma unroll
    for (int o = 16; o; o >>= 1) v += __shfl_xor_sync(0xffffffffu, v, o);
    if ((tid & 31) == 0) s8[tid >> 5] = v;
    __syncthreads();
    float r = s8[0]+s8[1]+s8[2]+s8[3]+s8[4]+s8[5]+s8[6]+s8[7];
    __syncthreads();
    return r;
}

// ---------------- kernel: LN reduce ----------------
__global__ __launch_bounds__(256) void lnred_kernel(const float* __restrict__ ln_g,
                             const float* __restrict__ ln_b) {
    __shared__ float s8[8];
    int t = blockIdx.x;
    int tid = threadIdx.x;
    float v = g_bias2[tid];
    #pragma unroll
    for (int sl = 0; sl < NSL; sl++)
        v += g_part[((size_t)sl * NBC + t) * EE + tid];
    float mu = blk_sum256(v, s8, tid) * (1.f/EE);
    float d = v - mu;
    float var = blk_sum256(d*d, s8, tid) * (1.f/EE);
    g_ln[(size_t)t * EE + tid] = d * rsqrtf(var + LN_EPS) * ln_g[tid] + ln_b[tid];
}

// ---------------- kernel: FFN hidden (cp.async double-buffered) ----------------
__global__ __launch_bounds__(256) void ffn1_kernel(const float* __restrict__ b1) {
    __shared__ __align__(16) float s_lnT[EE][8];     // 8KB, [e][token]
    __shared__ __align__(16) float s_buf[8704];      // union: weights 2x(64x68) | s_acc[16][8][68]
    int t0 = blockIdx.x * TOK, slice = blockIdx.y;
    int tid = threadIdx.x;
    int jc = tid & 15, eg = tid >> 4;

    // chunk = 64 e rows x 16 quads (of W1T columns slice*64..+64), row stride 68 floats
    const float4* Wg = (const float4*)g_W1T + slice*16;   // + e*256 per row

    #pragma unroll
    for (int r = 0; r < 4; r++) {
        int idx = r*256 + tid;
        int row = idx >> 4, q = idx & 15;
        cp_async16(&s_buf[row*68 + q*4], Wg + (size_t)row * 256 + q);
    }
    cp_commit();

    // load ln transposed: s_lnT[e][t]
    #pragma unroll
    for (int r = 0; r < 8; r++) {
        int idx = r*256 + tid;
        int t = idx >> 8, e = idx & 255;
        s_lnT[e][t] = g_ln[(size_t)(t0 + t) * EE + e];
    }

    float4 a[TOK];
    #pragma unroll
    for (int tt = 0; tt < TOK; tt++) a[tt] = make_float4(0.f,0.f,0.f,0.f);

    #pragma unroll
    for (int c = 0; c < 4; c++) {
        if (c < 3) {
            const float4* src = Wg + (size_t)(c+1) * 64 * 256;
            float* dst = &s_buf[((c+1)&1)*4352];
            #pragma unroll
            for (int r = 0; r < 4; r++) {
                int idx = r*256 + tid;
                int row = idx >> 4, q = idx & 15;
                cp_async16(dst + row*68 + q*4, src + (size_t)row * 256 + q);
            }
            cp_commit();
            cp_wait1();
        } else {
            cp_wait0();
        }
        __syncthreads();
        const float* wb = &s_buf[(c&1)*4352];
        #pragma unroll
        for (int i = 0; i < 4; i++) {
            int el = eg*4 + i;
            float4 m  = *(const float4*)&wb[el*68 + jc*4];
            float4 tA = *(const float4*)&s_lnT[c*64 + el][0];
            float4 tB = *(const float4*)&s_lnT[c*64 + el][4];
            ACC8(m, tA, tB);
        }
        __syncthreads();
    }

    // reduce 16 eg groups via overlay s_acc[16][8][68]
    float* s_acc = s_buf;
    #pragma unroll
    for (int tt = 0; tt < TOK; tt++)
        *(float4*)&s_acc[(eg*TOK + tt)*68 + jc*4] = a[tt];
    __syncthreads();

    #pragma unroll
    for (int r = 0; r < 2; r++) {
        int idx = r*256 + tid;
        int tt = idx >> 6, jj = idx & 63;
        float s = 0.f;
        #pragma unroll
        for (int g = 0; g < 16; g++) s += s_acc[(g*TOK + tt)*68 + jj];
        g_hid[(size_t)(t0 + tt) * HID + slice*64 + jj] = fmaxf(s + b1[slice*64 + jj], 0.f);
    }
}

// ---------------- kernel: FFN out partial GEMM (cp.async double-buffered) ----------------
__global__ __launch_bounds__(256) void ffn2_kernel() {
    __shared__ __align__(16) float s_hT[64][8];
    __shared__ __align__(16) float s_buf[8320];
    int t0 = blockIdx.x * TOK, slice = blockIdx.y;
    int tid = threadIdx.x;
    int fc = tid & 63, jg = tid >> 6;

    const float4* Wg = (const float4*)g_W2T + (size_t)(slice*64) * 64;

    #pragma unroll
    for (int r = 0; r < 4; r++) {
        int idx = r*256 + tid;
        cp_async16(&s_buf[idx*4], Wg + idx);
    }
    cp_commit();

    #pragma unroll
    for (int r = 0; r < 2; r++) {
        int idx = r*256 + tid;
        int t = idx >> 6, j = idx & 63;
        s_hT[j][t] = g_hid[(size_t)(t0 + t) * HID + slice*64 + j];
    }

    float4 a[TOK];
    #pragma unroll
    for (int tt = 0; tt < TOK; tt++) a[tt] = make_float4(0.f,0.f,0.f,0.f);

    #pragma unroll
    for (int c = 0; c < 4; c++) {
        if (c < 3) {
            const float4* src = Wg + (c+1)*1024;
            float* dst = &s_buf[((c+1)&1)*4096];
            #pragma unroll
            for (int r = 0; r < 4; r++) {
                int idx = r*256 + tid;
                cp_async16(dst + idx*4, src + idx);
            }
            cp_commit();
            cp_wait1();
        } else {
            cp_wait0();
        }
        __syncthreads();
        const float* wb = &s_buf[(c&1)*4096];
        #pragma unroll
        for (int jl = 0; jl < 4; jl++) {
            int j = jg*4 + jl;
            float4 m  = *(const float4*)&wb[(j*64 + fc)*4];
            float4 tA = *(const float4*)&s_hT[c*16 + j][0];
            float4 tB = *(const float4*)&s_hT[c*16 + j][4];
            ACC8(m, tA, tB);
        }
        __syncthreads();
    }

    float* s_acc = s_buf;
    #pragma unroll
    for (int tt = 0; tt < TOK; tt++)
        *(float4*)&s_acc[(jg*TOK + tt)*260 + fc*4] = a[tt];
    __syncthreads();
    int f = tid;
    #pragma unroll
    for (int tt = 0; tt < TOK; tt++) {
        float s = s_acc[(0*TOK+tt)*260 + f] + s_acc[(1*TOK+tt)*260 + f]
                + s_acc[(2*TOK+tt)*260 + f] + s_acc[(3*TOK+tt)*260 + f];
        g_part2[((size_t)slice * NBC + t0 + tt) * EE + f] = s;
    }
}

// ---------------- kernel: final reduce + residual + mask ----------------
__global__ __launch_bounds__(256) void outred_kernel(const float* __restrict__ b2,
                              const int* __restrict__ real_cols,
                              float* __restrict__ out) {
    int t = blockIdx.x;
    int tid = threadIdx.x;
    int bidx = t >> 5, cidx = t & 31;
    bool valid = cidx < real_cols[bidx];
    float s = b2[tid] + g_ln[(size_t)t * EE + tid];
    #pragma unroll
    for (int sl = 0; sl < NSL; sl++)
        s += g_part2[((size_t)sl * NBC + t) * EE + tid];
    out[(size_t)t * EE + tid] = valid ? s : 0.f;
}

// ---------------- launch ----------------
extern "C" void kernel_launch(void* const* d_in, const int* in_sizes, int n_in,
                              void* d_out, int out_size) {
    const float* x         = (const float*)d_in[0];
    const int*   real_cols = (const int*)  d_in[1];
    const int*   real_rows = (const int*)  d_in[2];
    const float* cls       = (const float*)d_in[3];
    const float* w_qkv     = (const float*)d_in[4];
    const float* b_qkv     = (const float*)d_in[5];
    const float* w_out     = (const float*)d_in[6];
    const float* b_out     = (const float*)d_in[7];
    const float* ln_g      = (const float*)d_in[8];
    const float* ln_b      = (const float*)d_in[9];
    const float* w1        = (const float*)d_in[10];
    const float* b1        = (const float*)d_in[11];
    const float* w2        = (const float*)d_in[12];
    const float* b2        = (const float*)d_in[13];
    float* out = (float*)d_out;

    prep1_kernel<<<8, 256>>>(cls, w_qkv, b_qkv);
    setup_kernel<<<593, 256>>>(w_qkv, b_qkv, w_out, b_out, w1, w2);
    attn_kernel<<<NBC, 1024>>>(x, real_rows, cls);
    mha_part_kernel<<<dim3(NBC/TOK, NSL), 256>>>();
    lnred_kernel<<<NBC, 256>>>(ln_g, ln_b);
    ffn1_kernel<<<dim3(NBC/TOK, NSL), 256>>>(b1);
    ffn2_kernel<<<dim3(NBC/TOK, NSL), 256>>>();
    outred_kernel<<<NBC, 256>>>(b2, real_cols, out);
}